// round 9
// baseline (speedup 1.0000x reference)
#include <cuda_runtime.h>
#include <math.h>

#define BATCH 2
#define SEQ   2048
#define EMB   4096
#define NH    32
#define NKV   8
#define HD    128
#define MROWS (BATCH*SEQ)     /* 4096 */
#define KVE   (NKV*HD)        /* 1024 */

/* ---------------- scratch (allocation-free: __device__ globals) ---------------- */
__device__ float g_qp[(size_t)MROWS*EMB];    /* 64 MB  q pre/post rope, [b*S+s][h*128+d] */
__device__ float g_kp[(size_t)MROWS*KVE];    /* 16 MB  k                                 */
__device__ float g_vp[(size_t)MROWS*KVE];    /* 16 MB  v                                 */
__device__ float g_attn[(size_t)MROWS*EMB];  /* 64 MB  attention output                  */
__device__ float g_cos[SEQ*64];
__device__ float g_sin[SEQ*64];

/* ---------------- helpers ---------------- */
__device__ __forceinline__ float tf32r(float x) {
    unsigned u;
    asm("cvt.rna.tf32.f32 %0, %1;" : "=r"(u) : "f"(x));
    return __uint_as_float(u);
}

__device__ __forceinline__ void mma8(float* d, const unsigned* a, const unsigned* b) {
    asm volatile(
        "mma.sync.aligned.m16n8k8.row.col.f32.tf32.tf32.f32 "
        "{%0,%1,%2,%3}, {%4,%5,%6,%7}, {%8,%9}, {%0,%1,%2,%3};\n"
        : "+f"(d[0]), "+f"(d[1]), "+f"(d[2]), "+f"(d[3])
        : "r"(a[0]), "r"(a[1]), "r"(a[2]), "r"(a[3]), "r"(b[0]), "r"(b[1]));
}

/* ---------------- RoPE cos/sin table (fp32, mirrors the reference) ---------------- */
__global__ void rope_table_kernel(const int* __restrict__ pos) {
    int i = blockIdx.x * blockDim.x + threadIdx.x;
    if (i >= SEQ * 64) return;
    int s = i >> 6, d = i & 63;
    float e = (float)d * (1.0f / 64.0f);
    float invf = powf(500000.0f, -e);
    float ang = (float)pos[s] * invf;
    float sv, cv;
    sincosf(ang, &sv, &cv);
    g_cos[i] = cv;
    g_sin[i] = sv;
}

/* ---------------- in-place RoPE over [row][h*128+d] ---------------- */
__global__ void rope_apply_kernel(float* __restrict__ buf, int nh) {
    int row = blockIdx.x;              /* 0..MROWS-1 */
    int s = row & (SEQ - 1);
    float* p = buf + (size_t)row * nh * HD;
    for (int idx = threadIdx.x; idx < nh * 64; idx += blockDim.x) {
        int h = idx >> 6, d = idx & 63;
        float x1 = p[h * HD + d];
        float x2 = p[h * HD + d + 64];
        float c  = g_cos[s * 64 + d];
        float sn = g_sin[s * 64 + d];
        p[h * HD + d]      = x1 * c - x2 * sn;
        p[h * HD + d + 64] = x2 * c + x1 * sn;
    }
}

/* ---------------- TF32 GEMM: C[M,N] = A[M,K] * W[N,K]^T ----------------
 * BM=BN=128, BK=32, 256 threads (8 warps: 4(M) x 2(N), warp tile 32x64).
 * Register double-buffered global loads; padded smem -> conflict-free frags. */
__global__ void __launch_bounds__(256, 1)
gemm_tf32_kernel(const float* __restrict__ A, const float* __restrict__ W,
                 float* __restrict__ C, int N, int K)
{
    __shared__ float As[128][36];
    __shared__ float Bs[128][36];

    const int tid  = threadIdx.x;
    const int lane = tid & 31, warp = tid >> 5;
    const int m0 = blockIdx.y * 128, n0 = blockIdx.x * 128;
    const int wm = (warp >> 1) * 32;     /* warp M offset */
    const int wn = (warp & 1) * 64;      /* warp N offset */
    const int g  = lane >> 2, tg = lane & 3;

    const int lr = tid >> 3;             /* 0..31 */
    const int lc = (tid & 7) << 2;       /* 0,4,...,28 */
    const float* Ap = A + (size_t)(m0 + lr) * K + lc;
    const float* Wp = W + (size_t)(n0 + lr) * K + lc;

    float acc[2][8][4];
#pragma unroll
    for (int i = 0; i < 2; i++)
#pragma unroll
        for (int j = 0; j < 8; j++)
#pragma unroll
            for (int l = 0; l < 4; l++) acc[i][j][l] = 0.0f;

    float4 ra[4], rb[4];
#pragma unroll
    for (int i = 0; i < 4; i++) {
        ra[i] = *(const float4*)(Ap + (size_t)i * 32 * K);
        rb[i] = *(const float4*)(Wp + (size_t)i * 32 * K);
    }
#pragma unroll
    for (int i = 0; i < 4; i++) {
        As[lr + i * 32][lc + 0] = tf32r(ra[i].x);
        As[lr + i * 32][lc + 1] = tf32r(ra[i].y);
        As[lr + i * 32][lc + 2] = tf32r(ra[i].z);
        As[lr + i * 32][lc + 3] = tf32r(ra[i].w);
        Bs[lr + i * 32][lc + 0] = tf32r(rb[i].x);
        Bs[lr + i * 32][lc + 1] = tf32r(rb[i].y);
        Bs[lr + i * 32][lc + 2] = tf32r(rb[i].z);
        Bs[lr + i * 32][lc + 3] = tf32r(rb[i].w);
    }
    __syncthreads();

    const int nk = K >> 5;
    for (int kt = 0; kt < nk; ++kt) {
        if (kt + 1 < nk) {
            const float* Ap2 = Ap + (kt + 1) * 32;
            const float* Wp2 = Wp + (kt + 1) * 32;
#pragma unroll
            for (int i = 0; i < 4; i++) {
                ra[i] = *(const float4*)(Ap2 + (size_t)i * 32 * K);
                rb[i] = *(const float4*)(Wp2 + (size_t)i * 32 * K);
            }
        }
#pragma unroll
        for (int ks = 0; ks < 4; ++ks) {
            const int k = ks * 8;
            unsigned af[2][4];
#pragma unroll
            for (int mt = 0; mt < 2; ++mt) {
                int r = wm + mt * 16 + g;
                af[mt][0] = __float_as_uint(As[r][k + tg]);
                af[mt][1] = __float_as_uint(As[r + 8][k + tg]);
                af[mt][2] = __float_as_uint(As[r][k + 4 + tg]);
                af[mt][3] = __float_as_uint(As[r + 8][k + 4 + tg]);
            }
#pragma unroll
            for (int nt = 0; nt < 8; ++nt) {
                int cN = wn + nt * 8 + g;
                unsigned bf[2];
                bf[0] = __float_as_uint(Bs[cN][k + tg]);
                bf[1] = __float_as_uint(Bs[cN][k + 4 + tg]);
                mma8(acc[0][nt], af[0], bf);
                mma8(acc[1][nt], af[1], bf);
            }
        }
        __syncthreads();
        if (kt + 1 < nk) {
#pragma unroll
            for (int i = 0; i < 4; i++) {
                As[lr + i * 32][lc + 0] = tf32r(ra[i].x);
                As[lr + i * 32][lc + 1] = tf32r(ra[i].y);
                As[lr + i * 32][lc + 2] = tf32r(ra[i].z);
                As[lr + i * 32][lc + 3] = tf32r(ra[i].w);
                Bs[lr + i * 32][lc + 0] = tf32r(rb[i].x);
                Bs[lr + i * 32][lc + 1] = tf32r(rb[i].y);
                Bs[lr + i * 32][lc + 2] = tf32r(rb[i].z);
                Bs[lr + i * 32][lc + 3] = tf32r(rb[i].w);
            }
        }
        __syncthreads();
    }

#pragma unroll
    for (int mt = 0; mt < 2; ++mt) {
        int r0 = m0 + wm + mt * 16 + g;
#pragma unroll
        for (int nt = 0; nt < 8; ++nt) {
            int cN = n0 + wn + nt * 8 + 2 * tg;
            *(float2*)(C + (size_t)r0 * N + cN)       = make_float2(acc[mt][nt][0], acc[mt][nt][1]);
            *(float2*)(C + (size_t)(r0 + 8) * N + cN) = make_float2(acc[mt][nt][2], acc[mt][nt][3]);
        }
    }
}

/* ---------------- causal flash attention (GQA), TF32 mma ----------------
 * CTA: 128 q rows of one (b,h). 8 warps x 16 q rows. kv tiles of 64. */
#define ATTN_SMEM_FLOATS (128*132 + 64*132 + 64*132 + 128*68)
#define ATTN_SMEM_BYTES  (ATTN_SMEM_FLOATS * 4)

__global__ void __launch_bounds__(256, 1) attn_kernel() {
    extern __shared__ float sm[];
    float* Qs = sm;                      /* [128][132] */
    float* Ks = Qs + 128 * 132;          /* [64][132]  */
    float* Vs = Ks + 64 * 132;           /* [64][132]  */
    float* Ps = Vs + 64 * 132;           /* [128][68]  */

    const int tid  = threadIdx.x;
    const int lane = tid & 31, warp = tid >> 5;
    const int g = lane >> 2, tg = lane & 3;
    const int qt = blockIdx.x, h = blockIdx.y, b = blockIdx.z;
    const int q0 = qt * 128;
    const int kvh = h >> 2;

    const float* qbase = g_qp + (size_t)b * SEQ * EMB + (size_t)h * HD;
    const float* kbase = g_kp + (size_t)b * SEQ * KVE + (size_t)kvh * HD;
    const float* vbase = g_vp + (size_t)b * SEQ * KVE + (size_t)kvh * HD;

    /* load Q tile (tf32-rounded) */
#pragma unroll
    for (int i = 0; i < 16; i++) {
        int lin = tid + i * 256;
        int r = lin >> 5;
        int c = (lin & 31) << 2;
        float4 v = *(const float4*)(qbase + (size_t)(q0 + r) * EMB + c);
        Qs[r * 132 + c + 0] = tf32r(v.x);
        Qs[r * 132 + c + 1] = tf32r(v.y);
        Qs[r * 132 + c + 2] = tf32r(v.z);
        Qs[r * 132 + c + 3] = tf32r(v.w);
    }

    float o[16][4];
#pragma unroll
    for (int i = 0; i < 16; i++)
#pragma unroll
        for (int j = 0; j < 4; j++) o[i][j] = 0.0f;

    float mi0 = -1e30f, mi1 = -1e30f, li0 = 0.0f, li1 = 0.0f;
    const int rowl0 = warp * 16 + g;
    const float SC = 0.08838834764831845f;  /* 1/sqrt(128) */
    const int nkt = 2 * qt + 2;

    for (int kt = 0; kt < nkt; ++kt) {
        const int k0 = kt * 64;
        __syncthreads();
#pragma unroll
        for (int i = 0; i < 8; i++) {
            int lin = lin = tid + i * 256;
            int r = lin >> 5;
            int c = (lin & 31) << 2;
            float4 kv4 = *(const float4*)(kbase + (size_t)(k0 + r) * KVE + c);
            Ks[r * 132 + c + 0] = tf32r(kv4.x);
            Ks[r * 132 + c + 1] = tf32r(kv4.y);
            Ks[r * 132 + c + 2] = tf32r(kv4.z);
            Ks[r * 132 + c + 3] = tf32r(kv4.w);
            float4 vv4 = *(const float4*)(vbase + (size_t)(k0 + r) * KVE + c);
            Vs[r * 132 + c + 0] = tf32r(vv4.x);
            Vs[r * 132 + c + 1] = tf32r(vv4.y);
            Vs[r * 132 + c + 2] = tf32r(vv4.z);
            Vs[r * 132 + c + 3] = tf32r(vv4.w);
        }
        __syncthreads();

        /* S = Q K^T  (16 x 64 per warp) */
        float sacc[8][4];
#pragma unroll
        for (int i = 0; i < 8; i++)
#pragma unroll
            for (int j = 0; j < 4; j++) sacc[i][j] = 0.0f;

#pragma unroll
        for (int ks = 0; ks < 16; ++ks) {
            const int k = ks * 8;
            unsigned af[4];
            af[0] = __float_as_uint(Qs[rowl0 * 132 + k + tg]);
            af[1] = __float_as_uint(Qs[(rowl0 + 8) * 132 + k + tg]);
            af[2] = __float_as_uint(Qs[rowl0 * 132 + k + 4 + tg]);
            af[3] = __float_as_uint(Qs[(rowl0 + 8) * 132 + k + 4 + tg]);
#pragma unroll
            for (int nt = 0; nt < 8; ++nt) {
                int cN = nt * 8 + g;
                unsigned bf[2];
                bf[0] = __float_as_uint(Ks[cN * 132 + k + tg]);
                bf[1] = __float_as_uint(Ks[cN * 132 + k + 4 + tg]);
                mma8(sacc[nt], af, bf);
            }
        }

        /* scale + causal mask + online softmax update */
        const int qg0 = q0 + rowl0, qg1 = qg0 + 8;
        float rmax0 = -1e30f, rmax1 = -1e30f;
#pragma unroll
        for (int nt = 0; nt < 8; ++nt) {
            int c0 = k0 + nt * 8 + 2 * tg;
            float v0 = sacc[nt][0] * SC; if (c0     > qg0) v0 = -1e30f;
            float v1 = sacc[nt][1] * SC; if (c0 + 1 > qg0) v1 = -1e30f;
            float v2 = sacc[nt][2] * SC; if (c0     > qg1) v2 = -1e30f;
            float v3 = sacc[nt][3] * SC; if (c0 + 1 > qg1) v3 = -1e30f;
            sacc[nt][0] = v0; sacc[nt][1] = v1; sacc[nt][2] = v2; sacc[nt][3] = v3;
            rmax0 = fmaxf(rmax0, fmaxf(v0, v1));
            rmax1 = fmaxf(rmax1, fmaxf(v2, v3));
        }
#pragma unroll
        for (int off = 1; off < 4; off <<= 1) {
            rmax0 = fmaxf(rmax0, __shfl_xor_sync(0xffffffffu, rmax0, off));
            rmax1 = fmaxf(rmax1, __shfl_xor_sync(0xffffffffu, rmax1, off));
        }
        float mn0 = fmaxf(mi0, rmax0), mn1 = fmaxf(mi1, rmax1);
        float al0 = __expf(mi0 - mn0), al1 = __expf(mi1 - mn1);
        float rs0 = 0.0f, rs1 = 0.0f;
#pragma unroll
        for (int nt = 0; nt < 8; ++nt) {
            float p0 = __expf(sacc[nt][0] - mn0);
            float p1 = __expf(sacc[nt][1] - mn0);
            float p2 = __expf(sacc[nt][2] - mn1);
            float p3 = __expf(sacc[nt][3] - mn1);
            rs0 += p0 + p1;
            rs1 += p2 + p3;
            int c = nt * 8 + 2 * tg;
            *(float2*)&Ps[rowl0 * 68 + c]       = make_float2(tf32r(p0), tf32r(p1));
            *(float2*)&Ps[(rowl0 + 8) * 68 + c] = make_float2(tf32r(p2), tf32r(p3));
        }
#pragma unroll
        for (int off = 1; off < 4; off <<= 1) {
            rs0 += __shfl_xor_sync(0xffffffffu, rs0, off);
            rs1 += __shfl_xor_sync(0xffffffffu, rs1, off);
        }
        li0 = li0 * al0 + rs0;
        li1 = li1 * al1 + rs1;
        mi0 = mn0; mi1 = mn1;
#pragma unroll
        for (int nt = 0; nt < 16; ++nt) {
            o[nt][0] *= al0; o[nt][1] *= al0;
            o[nt][2] *= al1; o[nt][3] *= al1;
        }
        __syncwarp();

        /* O += P V  (16 x 128 per warp) */
#pragma unroll
        for (int ks = 0; ks < 8; ++ks) {
            const int k = ks * 8;
            unsigned af[4];
            af[0] = __float_as_uint(Ps[rowl0 * 68 + k + tg]);
            af[1] = __float_as_uint(Ps[(rowl0 + 8) * 68 + k + tg]);
            af[2] = __float_as_uint(Ps[rowl0 * 68 + k + 4 + tg]);
            af[3] = __float_as_uint(Ps[(rowl0 + 8) * 68 + k + 4 + tg]);
#pragma unroll
            for (int nt = 0; nt < 16; ++nt) {
                int cN = nt * 8 + g;
                unsigned bf[2];
                bf[0] = __float_as_uint(Vs[(k + tg) * 132 + cN]);
                bf[1] = __float_as_uint(Vs[(k + 4 + tg) * 132 + cN]);
                mma8(o[nt], af, bf);
            }
        }
    }

    /* epilogue: normalize + write g_attn[b*S+s][h*128+d] */
    float inv0 = 1.0f / li0, inv1 = 1.0f / li1;
    float* obase = g_attn + (size_t)b * SEQ * EMB + (size_t)h * HD;
#pragma unroll
    for (int nt = 0; nt < 16; ++nt) {
        int d = nt * 8 + 2 * tg;
        *(float2*)(obase + (size_t)(q0 + rowl0) * EMB + d) =
            make_float2(o[nt][0] * inv0, o[nt][1] * inv0);
        *(float2*)(obase + (size_t)(q0 + rowl0 + 8) * EMB + d) =
            make_float2(o[nt][2] * inv1, o[nt][3] * inv1);
    }
}

/* ---------------- launch ---------------- */
extern "C" void kernel_launch(void* const* d_in, const int* in_sizes, int n_in,
                              void* d_out, int out_size)
{
    (void)in_sizes; (void)n_in; (void)out_size;
    const float* x   = (const float*)d_in[0];
    const float* wq  = (const float*)d_in[1];
    const float* wk  = (const float*)d_in[2];
    const float* wv  = (const float*)d_in[3];
    const float* wo  = (const float*)d_in[4];
    const int*   pos = (const int*)d_in[5];
    float* out = (float*)d_out;

    float *qp, *kp, *vp, *attn;
    cudaGetSymbolAddress((void**)&qp,   g_qp);
    cudaGetSymbolAddress((void**)&kp,   g_kp);
    cudaGetSymbolAddress((void**)&vp,   g_vp);
    cudaGetSymbolAddress((void**)&attn, g_attn);

    cudaFuncSetAttribute(attn_kernel, cudaFuncAttributeMaxDynamicSharedMemorySize,
                         ATTN_SMEM_BYTES);

    rope_table_kernel<<<(SEQ * 64 + 255) / 256, 256>>>(pos);

    gemm_tf32_kernel<<<dim3(EMB / 128, MROWS / 128), 256>>>(x, wq, qp, EMB, EMB);
    gemm_tf32_kernel<<<dim3(KVE / 128, MROWS / 128), 256>>>(x, wk, kp, KVE, EMB);
    gemm_tf32_kernel<<<dim3(KVE / 128, MROWS / 128), 256>>>(x, wv, vp, KVE, EMB);

    rope_apply_kernel<<<MROWS, 256>>>(qp, NH);
    rope_apply_kernel<<<MROWS, 256>>>(kp, NKV);

    attn_kernel<<<dim3(SEQ / 128, NH, BATCH), 256, ATTN_SMEM_BYTES>>>();

    gemm_tf32_kernel<<<dim3(EMB / 128, MROWS / 128), 256>>>(attn, wo, out, EMB, EMB);
}